// round 1
// baseline (speedup 1.0000x reference)
#include <cuda_runtime.h>
#include <math.h>

#define D        256
#define M_CODES  1024
#define N_TOK    65536
#define BM       128
#define BN       64
#define XS_LD    136      // 128 rows + 8 pad (k-major X tile)
#define ES_LD    257      // 256 + 1 pad (odd -> conflict-free code-strided reads)

// ---------------- scratch (no allocations allowed) ----------------
__device__ float g_normX[N_TOK];
__device__ float g_normE[M_CODES];
__device__ int   g_indices[N_TOK];
__device__ float g_counts[M_CODES];
__device__ float g_sumsq;

// ---------------- f32x2 packed helpers ----------------
static __device__ __forceinline__ unsigned long long pk2(float a, float b) {
    unsigned long long r;
    asm("mov.b64 %0, {%1,%2};" : "=l"(r) : "f"(a), "f"(b));
    return r;
}
static __device__ __forceinline__ float2 upk2(unsigned long long v) {
    float2 f;
    asm("mov.b64 {%0,%1}, %2;" : "=f"(f.x), "=f"(f.y) : "l"(v));
    return f;
}
static __device__ __forceinline__ unsigned long long ffma2(unsigned long long a,
                                                           unsigned long long b,
                                                           unsigned long long c) {
    unsigned long long d;
    asm("fma.rn.f32x2 %0, %1, %2, %3;" : "=l"(d) : "l"(a), "l"(b), "l"(c));
    return d;
}

// ---------------- init: zero histogram + loss accumulator ----------------
__global__ void init_kernel() {
    int t = threadIdx.x;
    if (t < M_CODES) g_counts[t] = 0.0f;
    if (t == 0) g_sumsq = 0.0f;
}

// ---------------- row sum-of-squares (x rows or embedding rows) ----------------
// block = 256 threads = 8 warps, one row per warp, 256 floats per row
__global__ void norms_kernel(const float* __restrict__ a, int which) {
    int warp = threadIdx.x >> 5, lane = threadIdx.x & 31;
    int row = blockIdx.x * 8 + warp;
    const float4* r4 = (const float4*)(a + ((size_t)row << 8));
    float s = 0.0f;
#pragma unroll
    for (int j = 0; j < 2; ++j) {
        float4 v = r4[lane + 32 * j];
        s += v.x * v.x + v.y * v.y + v.z * v.z + v.w * v.w;
    }
#pragma unroll
    for (int o = 16; o > 0; o >>= 1) s += __shfl_xor_sync(0xffffffffu, s, o);
    if (lane == 0) {
        if (which == 0) g_normX[row] = s;
        else            g_normE[row] = s;
    }
}

// ---------------- fused distance-GEMM + argmin ----------------
// Tile: BM=128 rows x BN=64 codes, full K=256 resident.
// Thread (tx,ty): 8 rows (4 f32x2 pairs) x 4 codes (c = mBase + tx + p*16).
// Distances replicate jax rounding: d = fl(fl(nX+nE) - 2*dot), ties -> lowest index.
__global__ __launch_bounds__(256, 1)
void argmin_kernel(const float* __restrict__ x, const float* __restrict__ emb,
                   float* __restrict__ d_out, long long idx_off, int write_idx) {
    extern __shared__ float sm[];
    float* Xs = sm;                    // [256][XS_LD] k-major, XOR-swizzled rows
    float* Es = sm + 256 * XS_LD;      // [BN][ES_LD] code-major

    int tid = threadIdx.x;
    int tx = tid & 15, ty = tid >> 4;
    int row0 = blockIdx.x * BM;
    int ty8 = ty * 8;

    // load + transpose X tile (gmem coalesced, swizzled smem writes)
    for (int li = tid; li < BM * (D / 4); li += 256) {
        int r = li >> 6, k4 = li & 63, k = k4 << 2;
        float4 v = ((const float4*)(x + ((size_t)(row0 + r) << 8)))[k4];
        int s = (k4 & 7) << 1;  // = ((k>>2)&7)<<1, same for k..k+3
        Xs[(k + 0) * XS_LD + (r ^ s)] = v.x;
        Xs[(k + 1) * XS_LD + (r ^ s)] = v.y;
        Xs[(k + 2) * XS_LD + (r ^ s)] = v.z;
        Xs[(k + 3) * XS_LD + (r ^ s)] = v.w;
    }

    float nx[8];
#pragma unroll
    for (int j = 0; j < 8; ++j) nx[j] = g_normX[row0 + ty8 + j];

    float bV[8]; int bI[8];
#pragma unroll
    for (int j = 0; j < 8; ++j) { bV[j] = 3.4e38f; bI[j] = 0x7fffffff; }

    for (int mt = 0; mt < M_CODES / BN; ++mt) {
        int mBase = mt * BN;
        __syncthreads();  // previous iter's reads done before Es overwrite (also covers Xs on iter 0)
        for (int li = tid; li < BN * (D / 4); li += 256) {
            int c = li >> 6, k4 = li & 63, k = k4 << 2;
            float4 v = ((const float4*)(emb + ((size_t)(mBase + c) << 8)))[k4];
            float* ep = &Es[c * ES_LD + k];
            ep[0] = v.x; ep[1] = v.y; ep[2] = v.z; ep[3] = v.w;
        }
        __syncthreads();

        unsigned long long acc[4][4];
#pragma unroll
        for (int j = 0; j < 4; ++j)
#pragma unroll
            for (int p = 0; p < 4; ++p) acc[j][p] = 0ull;  // (0.f, 0.f)

#pragma unroll 8
        for (int k = 0; k < D; ++k) {
            int s = ((k >> 2) & 7) << 1;
            const float* xk = &Xs[k * XS_LD];
            unsigned long long xp[4];
#pragma unroll
            for (int j = 0; j < 4; ++j)
                xp[j] = *(const unsigned long long*)&xk[(ty8 + 2 * j) ^ s];
#pragma unroll
            for (int p = 0; p < 4; ++p) {
                float ev = Es[(tx + p * 16) * ES_LD + k];
                unsigned long long ep = pk2(ev, ev);
#pragma unroll
                for (int j = 0; j < 4; ++j) acc[j][p] = ffma2(xp[j], ep, acc[j][p]);
            }
        }

        // epilogue: jax-rounded distances + running argmin (ascending code order)
#pragma unroll
        for (int p = 0; p < 4; ++p) {
            int c = mBase + tx + p * 16;
            float ne = g_normE[c];
#pragma unroll
            for (int j = 0; j < 4; ++j) {
                float2 dt = upk2(acc[j][p]);
                float d0 = (nx[2 * j]     + ne) - 2.0f * dt.x;
                float d1 = (nx[2 * j + 1] + ne) - 2.0f * dt.y;
                if (d0 < bV[2 * j])     { bV[2 * j] = d0;     bI[2 * j] = c; }
                if (d1 < bV[2 * j + 1]) { bV[2 * j + 1] = d1; bI[2 * j + 1] = c; }
            }
        }
    }

    // cross-thread reduce per row (16 tx lanes per row), lowest-index tie break
    __syncthreads();
    float* rV = Xs;                 // reuse [128][16]
    int*   rI = (int*)(Xs + 2048);  // [128][16]
#pragma unroll
    for (int j = 0; j < 8; ++j) {
        rV[(ty8 + j) * 16 + tx] = bV[j];
        rI[(ty8 + j) * 16 + tx] = bI[j];
    }
    __syncthreads();
    if (tid < BM) {
        float bv = 3.4e38f; int bi = 0x7fffffff;
#pragma unroll
        for (int t = 0; t < 16; ++t) {
            float v = rV[tid * 16 + t]; int i = rI[tid * 16 + t];
            if (v < bv || (v == bv && i < bi)) { bv = v; bi = i; }
        }
        int grow = row0 + tid;
        g_indices[grow] = bi;
        if (write_idx) d_out[idx_off + grow] = (float)bi;
    }
}

// ---------------- gather + straight-through + loss partials + histogram ----------------
__global__ void gather_kernel(const float* __restrict__ x, const float* __restrict__ emb,
                              float* __restrict__ qst_out) {
    int warp = threadIdx.x >> 5, lane = threadIdx.x & 31;
    int row = blockIdx.x * 8 + warp;
    int idx = g_indices[row];
    const float4* e4 = (const float4*)(emb + ((size_t)idx << 8));
    const float4* x4 = (const float4*)(x + ((size_t)row << 8));
    float4* o4 = (float4*)(qst_out + ((size_t)row << 8));
    float s = 0.0f;
#pragma unroll
    for (int j = 0; j < 2; ++j) {
        float4 q = e4[lane + 32 * j];
        float4 xv = x4[lane + 32 * j];
        float4 o;
        // replicate x + (q - x) rounding (NOT just q)
        o.x = xv.x + (q.x - xv.x);
        o.y = xv.y + (q.y - xv.y);
        o.z = xv.z + (q.z - xv.z);
        o.w = xv.w + (q.w - xv.w);
        o4[lane + 32 * j] = o;
        float dx = xv.x - q.x, dy = xv.y - q.y, dz = xv.z - q.z, dw = xv.w - q.w;
        s += dx * dx + dy * dy + dz * dz + dw * dw;
    }
#pragma unroll
    for (int o = 16; o > 0; o >>= 1) s += __shfl_xor_sync(0xffffffffu, s, o);
    if (lane == 0) {
        atomicAdd(&g_sumsq, s);
        atomicAdd(&g_counts[idx], 1.0f);
    }
}

// ---------------- loss + perplexity ----------------
__global__ void finalize_kernel(float* __restrict__ d_out, long long loss_off,
                                long long perp_off) {
    __shared__ float red[1024];
    int t = threadIdx.x;
    float p = g_counts[t] * (1.0f / (float)N_TOK);
    red[t] = p * logf(p + 1e-10f);
    __syncthreads();
    for (int s = 512; s > 0; s >>= 1) {
        if (t < s) red[t] += red[t + s];
        __syncthreads();
    }
    if (t == 0) {
        d_out[loss_off] = 0.25f * g_sumsq / ((float)N_TOK * (float)D);
        d_out[perp_off] = expf(-red[0]);
    }
}

// ---------------- launch ----------------
extern "C" void kernel_launch(void* const* d_in, const int* in_sizes, int n_in,
                              void* d_out, int out_size) {
    const float* x   = (const float*)d_in[0];
    const float* emb = (const float*)d_in[1];
    float* out = (float*)d_out;

    int NT = in_sizes[0] / D;                 // 65536 tokens
    long long qn = (long long)in_sizes[0];    // 16,777,216 quantized elems
    long long loss_off = qn;
    long long idx_off  = qn + 1;
    long long perp_off = qn + 1 + NT;
    int full = (out_size >= (int)(qn + NT + 2)) ? 1 : 0;

    int smem = (256 * XS_LD + BN * ES_LD) * (int)sizeof(float);
    cudaFuncSetAttribute(argmin_kernel, cudaFuncAttributeMaxDynamicSharedMemorySize, smem);

    init_kernel<<<1, 1024>>>();
    norms_kernel<<<NT / 8, 256>>>(x, 0);
    norms_kernel<<<M_CODES / 8, 256>>>(emb, 1);
    argmin_kernel<<<NT / BM, 256, smem>>>(x, emb, out, idx_off, full);
    gather_kernel<<<NT / 8, 256>>>(x, emb, out);
    if (full) finalize_kernel<<<1, 1024>>>(out, loss_off, perp_off);
}